// round 15
// baseline (speedup 1.0000x reference)
#include <cuda_runtime.h>
#include <cstdint>
#include <cstddef>

#define NB 4
#define P  2048
#define D  64
#define ITERS   50
// safe col pass geometry (it < 2)
#define RCH_S   32
#define JB_S    4
// 10 * log2(e)
#define K2E 14.4269504089f
// log2(1/2048 + 1e-8)
#define LOG_MU2 (-10.99997045f)
#define LOG_NU2 (-10.99997045f)
#define NEG_BIG (-3.0e38f)

__device__ __forceinline__ float ex2f(float x) {
    float r; asm("ex2.approx.f32 %0, %1;" : "=f"(r) : "f"(x)); return r;
}
__device__ __forceinline__ float lg2f(float x) {
    float r; asm("lg2.approx.f32 %0, %1;" : "=f"(r) : "f"(x)); return r;
}

// ---------------- static device scratch -----------------------------------
__device__ float g_us2[NB * P];
__device__ float g_vs2[NB * P];
__device__ float g_xx[NB * P];
__device__ float g_yy[NB * P];
__device__ float g_pm2[NB * RCH_S * P];    // safe col partial max
__device__ float g_ps2[NB * RCH_S * P];    // safe col partial sum
__device__ float g_psF[(size_t)NB * 64 * P]; // fast col partials (2 MB)
__device__ float g_cp[NB * 1024];
__device__ unsigned g_tick_s[NB * JB_S];   // safe path tickets (reset)
__device__ unsigned g_rowcnt[NB * 64];     // fast: monotone row-publish counters
__device__ unsigned g_tickM[NB * 2];       // fast: monotone v-combine tickets

// ---------------- init -------------------------------------------------------
__global__ void init_kernel() {
    int t = blockIdx.x * 256 + threadIdx.x;
    if (t < NB * P) g_vs2[t] = 0.0f;
    if (t < NB * JB_S) g_tick_s[t] = 0u;
    if (t < NB * 64) g_rowcnt[t] = 0u;
    if (t < NB * 2) g_tickM[t] = 0u;
}

// ---------------- squared norms ----------------------------------------------
__global__ __launch_bounds__(256) void norms_kernel(const float* __restrict__ x,
                                                    const float* __restrict__ y) {
    const int r = blockIdx.x * 256 + threadIdx.x;
    const float4* xr = (const float4*)(x + (size_t)r * D);
    const float4* yr = (const float4*)(y + (size_t)r * D);
    float ax = 0.0f, ay = 0.0f;
#pragma unroll
    for (int t = 0; t < D / 4; t++) {
        float4 a = xr[t], b = yr[t];
        ax = fmaf(a.x, a.x, ax); ax = fmaf(a.y, a.y, ax);
        ax = fmaf(a.z, a.z, ax); ax = fmaf(a.w, a.w, ax);
        ay = fmaf(b.x, b.x, ay); ay = fmaf(b.y, b.y, ay);
        ay = fmaf(b.z, b.z, ay); ay = fmaf(b.w, b.w, ay);
    }
    g_xx[r] = ax;
    g_yy[r] = ay;
}

// ---------------- C = xx_i + yy_j - 2*x.y ---------------------------------------
__global__ __launch_bounds__(256) void c_kernel(const float* __restrict__ x,
                                                const float* __restrict__ y,
                                                float* __restrict__ C) {
    __shared__ float Xs[64][68];
    __shared__ float Ys[64][68];
    const int tx = threadIdx.x, ty = threadIdx.y;
    const int tid = ty * 16 + tx;
    const int n  = blockIdx.z;
    const int i0 = blockIdx.y * 64;
    const int j0 = blockIdx.x * 64;

    {
        const int r  = tid >> 2;
        const int c4 = tid & 3;
        const float* xg = x + ((size_t)n * P + i0 + r) * D;
        const float* yg = y + ((size_t)n * P + j0 + r) * D;
#pragma unroll
        for (int q = 0; q < 4; q++) {
            int col = c4 * 16 + q * 4;
            *(float4*)&Xs[r][col] = *(const float4*)(xg + col);
            *(float4*)&Ys[r][col] = *(const float4*)(yg + col);
        }
    }
    __syncthreads();

    float acc[4][4];
#pragma unroll
    for (int a = 0; a < 4; a++)
#pragma unroll
        for (int b = 0; b < 4; b++) acc[a][b] = 0.0f;

#pragma unroll
    for (int k = 0; k < D; k += 4) {
        float4 xa[4], yb[4];
#pragma unroll
        for (int a = 0; a < 4; a++) xa[a] = *(float4*)&Xs[ty * 4 + a][k];
#pragma unroll
        for (int b = 0; b < 4; b++) yb[b] = *(float4*)&Ys[tx * 4 + b][k];
#pragma unroll
        for (int a = 0; a < 4; a++)
#pragma unroll
            for (int b = 0; b < 4; b++) {
                acc[a][b] = fmaf(xa[a].x, yb[b].x, acc[a][b]);
                acc[a][b] = fmaf(xa[a].y, yb[b].y, acc[a][b]);
                acc[a][b] = fmaf(xa[a].z, yb[b].z, acc[a][b]);
                acc[a][b] = fmaf(xa[a].w, yb[b].w, acc[a][b]);
            }
    }

    float yyv[4];
#pragma unroll
    for (int b = 0; b < 4; b++) yyv[b] = g_yy[(n << 11) + j0 + tx * 4 + b];

    float* Cb = C + (size_t)n * P * P;
#pragma unroll
    for (int a = 0; a < 4; a++) {
        float xxv = g_xx[(n << 11) + i0 + ty * 4 + a];
        float4 o;
        o.x = fmaf(-2.0f, acc[a][0], xxv + yyv[0]);
        o.y = fmaf(-2.0f, acc[a][1], xxv + yyv[1]);
        o.z = fmaf(-2.0f, acc[a][2], xxv + yyv[2]);
        o.w = fmaf(-2.0f, acc[a][3], xxv + yyv[3]);
        *(float4*)&Cb[(size_t)(i0 + ty * 4 + a) * P + j0 + tx * 4] = o;
    }
}

// ---------------- safe LSE helper -------------------------------------------------
__device__ __forceinline__ void lse_group(float4 c, float vx, float vy, float vz, float vw,
                                          float& m, float& s) {
    float b0 = fmaf(c.x, -K2E, vx);
    float b1 = fmaf(c.y, -K2E, vy);
    float b2 = fmaf(c.z, -K2E, vz);
    float b3 = fmaf(c.w, -K2E, vw);
    float cm = fmaxf(fmaxf(b0, b1), fmaxf(b2, b3));
    float mn = fmaxf(m, cm);
    s = fmaf(s, ex2f(m - mn),
             ex2f(b0 - mn) + ex2f(b1 - mn) + ex2f(b2 - mn) + ex2f(b3 - mn));
    m = mn;
}

// ================ SAFE path (it < 2) — proven R5 kernels ===========================
__global__ __launch_bounds__(256) void row_safe(const float* __restrict__ C) {
    __shared__ float vs[P];
    const int lane = threadIdx.x & 31;
    const int warp = threadIdx.x >> 5;
    const int row  = blockIdx.x * 8 + warp;
    const int n    = row >> 11;
    {
        const float4* src = (const float4*)(g_vs2 + (n << 11));
        float4* dst = (float4*)vs;
#pragma unroll
        for (int t = threadIdx.x; t < P / 4; t += 256) dst[t] = src[t];
    }
    __syncthreads();
    const float4* Crow = (const float4*)(C + (size_t)row * P);
    const float4* V4   = (const float4*)vs;
    float m0 = NEG_BIG, s0 = 0.0f, m1 = NEG_BIG, s1 = 0.0f;
#pragma unroll 4
    for (int k = 0; k < 8; k++) {
        const int t0 = lane + k * 64;
        const int t1 = t0 + 32;
        float4 c0 = Crow[t0];
        float4 c1 = Crow[t1];
        float4 v0 = V4[t0];
        float4 v1 = V4[t1];
        lse_group(c0, v0.x, v0.y, v0.z, v0.w, m0, s0);
        lse_group(c1, v1.x, v1.y, v1.z, v1.w, m1, s1);
    }
    float m = fmaxf(m0, m1);
    float s = s0 * ex2f(m0 - m) + s1 * ex2f(m1 - m);
#pragma unroll
    for (int o = 16; o; o >>= 1) {
        float mo = __shfl_xor_sync(0xffffffffu, m, o);
        float so = __shfl_xor_sync(0xffffffffu, s, o);
        float mn = fmaxf(m, mo);
        s = s * ex2f(m - mn) + so * ex2f(mo - mn);
        m = mn;
    }
    if (lane == 0) g_us2[row] = LOG_MU2 - (m + lg2f(s));
}

__global__ __launch_bounds__(256) void col_safe(const float* __restrict__ C) {
    __shared__ float us[P / RCH_S];
    __shared__ unsigned lastv;
    const int b     = blockIdx.x;
    const int jb    = b & (JB_S - 1);
    const int chunk = (b >> 2) & (RCH_S - 1);
    const int n     = b >> 7;
    const int j0    = (jb << 9) + (threadIdx.x << 1);
    const int i0    = chunk << 6;

    if (threadIdx.x < P / RCH_S)
        us[threadIdx.x] = g_us2[(n << 11) + i0 + threadIdx.x];
    __syncthreads();

    const float2* Cc = (const float2*)(C + (size_t)n * P * P + (size_t)i0 * P) + (j0 >> 1);
    const size_t po = ((size_t)n * RCH_S + chunk) * P + j0;

    float m0 = NEG_BIG, s0 = 0.0f, m1 = NEG_BIG, s1 = 0.0f;
#pragma unroll 4
    for (int i = 0; i < P / RCH_S; i += 4) {
        float2 r0 = Cc[(size_t)(i + 0) * (P / 2)];
        float2 r1 = Cc[(size_t)(i + 1) * (P / 2)];
        float2 r2 = Cc[(size_t)(i + 2) * (P / 2)];
        float2 r3 = Cc[(size_t)(i + 3) * (P / 2)];
        float4 c0 = {r0.x, r1.x, r2.x, r3.x};
        float4 c1 = {r0.y, r1.y, r2.y, r3.y};
        lse_group(c0, us[i], us[i + 1], us[i + 2], us[i + 3], m0, s0);
        lse_group(c1, us[i], us[i + 1], us[i + 2], us[i + 3], m1, s1);
    }
    g_pm2[po] = m0;     g_ps2[po] = s0;
    g_pm2[po + 1] = m1; g_ps2[po + 1] = s1;

    __threadfence();
    if (threadIdx.x == 0) lastv = atomicAdd(&g_tick_s[n * JB_S + jb], 1u);
    __syncthreads();
    if (lastv == RCH_S - 1) {
        __threadfence();
#pragma unroll
        for (int cc = 0; cc < 2; cc++) {
            const int j = j0 + cc;
            float mm = NEG_BIG;
#pragma unroll
            for (int c = 0; c < RCH_S; c++)
                mm = fmaxf(mm, __ldcg(&g_pm2[((size_t)n * RCH_S + c) * P + j]));
            float ss = 0.0f;
#pragma unroll
            for (int c = 0; c < RCH_S; c++) {
                size_t idx = ((size_t)n * RCH_S + c) * P + j;
                ss += __ldcg(&g_ps2[idx]) * ex2f(__ldcg(&g_pm2[idx]) - mm);
            }
            g_vs2[(n << 11) + j] = LOG_NU2 - (mm + lg2f(ss));
        }
        if (threadIdx.x == 0) g_tick_s[n * JB_S + jb] = 0u;
    }
}

// ================ FAST iteration (it >= 2): one launch, flag-pipelined =============
// 512 blocks x 256 threads.  Block (n, lb):
//   row phase: rows lb*16 .. lb*16+15 (ref-trick, R5-proven math)
//   col phase: chunk ch = lb>>1 (32 rows), jb = lb&1 (1024 cols, 4 cols/thread, float4)
// Monotone counters across per-iteration launches.
// Per (n, jb): 64 blocks -> tick target 64*(k+1)-1.
__global__ __launch_bounds__(256, 4) void iter_fast(const float* __restrict__ C, int k) {
    __shared__ float vs[P];
    __shared__ float us[32];
    __shared__ unsigned pretick;
    const int tid  = threadIdx.x;
    const int lane = tid & 31;
    const int warp = tid >> 5;
    const int n    = blockIdx.x >> 7;
    const int lb   = blockIdx.x & 127;
    const int ch   = lb >> 1;            // 0..63, 32-row chunk
    const int jb   = lb & 1;             // 0..1, 1024-col group

    // ---- load v (previous iteration, complete at kernel start) ------------------
    {
        const float4* src = (const float4*)(g_vs2 + (n << 11));
        float4* dst = (float4*)vs;
#pragma unroll
        for (int t = tid; t < P / 4; t += 256) dst[t] = src[t];
    }
    __syncthreads();

    // ---- row phase: 2 rows per warp, streaming -----------------------------------
    const float4* V4 = (const float4*)vs;
    {
        const int gA = (n << 11) + lb * 16 + warp * 2;
        const int gB = gA + 1;
        const float4* CrA = (const float4*)(C + (size_t)gA * P);
        const float4* CrB = (const float4*)(C + (size_t)gB * P);
        const float upA = g_us2[gA];
        const float upB = g_us2[gB];
        const float refA = LOG_MU2 - upA;
        const float refB = LOG_MU2 - upB;
        float a0 = 0, a1 = 0, a2 = 0, a3 = 0;
        float b0 = 0, b1 = 0, b2 = 0, b3 = 0;
#pragma unroll 4
        for (int t = lane; t < P / 4; t += 32) {
            float4 cA = CrA[t];
            float4 cB = CrB[t];
            float4 vv = V4[t];
            a0 += ex2f(fmaf(cA.x, -K2E, vv.x) - refA);
            a1 += ex2f(fmaf(cA.y, -K2E, vv.y) - refA);
            a2 += ex2f(fmaf(cA.z, -K2E, vv.z) - refA);
            a3 += ex2f(fmaf(cA.w, -K2E, vv.w) - refA);
            b0 += ex2f(fmaf(cB.x, -K2E, vv.x) - refB);
            b1 += ex2f(fmaf(cB.y, -K2E, vv.y) - refB);
            b2 += ex2f(fmaf(cB.z, -K2E, vv.z) - refB);
            b3 += ex2f(fmaf(cB.w, -K2E, vv.w) - refB);
        }
        float sA = (a0 + a1) + (a2 + a3);
        float sB = (b0 + b1) + (b2 + b3);
#pragma unroll
        for (int o = 16; o; o >>= 1) {
            sA += __shfl_xor_sync(0xffffffffu, sA, o);
            sB += __shfl_xor_sync(0xffffffffu, sB, o);
        }
        if (lane == 0) {
            g_us2[gA] = upA - lg2f(sA);
            g_us2[gB] = upB - lg2f(sB);
        }
    }
    // publish: all 16 rows of this block done (chunk ch gets +16 from each of 2 blocks)
    __syncthreads();
    __threadfence();
    if (tid == 0) atomicAdd(&g_rowcnt[n * 64 + (lb >> 1)], 16u);

    // ---- col phase: wait for own chunk's 32 rows ----------------------------------
    if (tid == 0) {
        const unsigned target = 32u * (unsigned)(k + 1);
        while (atomicAdd(&g_rowcnt[n * 64 + ch], 0u) < target) __nanosleep(32);
    }
    __syncthreads();
    __threadfence();
    if (tid < 32) us[tid] = __ldcg(&g_us2[(n << 11) + (ch << 5) + tid]);
    __syncthreads();

    const int j0 = (jb << 10) + (tid << 2);        // 4 cols per thread
    const float ref0 = LOG_NU2 - vs[j0];
    const float ref1 = LOG_NU2 - vs[j0 + 1];
    const float ref2 = LOG_NU2 - vs[j0 + 2];
    const float ref3 = LOG_NU2 - vs[j0 + 3];
    const float4* Cc = (const float4*)(C + (size_t)n * P * P + ((size_t)ch << 5) * P) + (j0 >> 2);

    float p0 = 0, p1 = 0, p2 = 0, p3 = 0;
    float q0 = 0, q1 = 0, q2 = 0, q3 = 0;
#pragma unroll 4
    for (int i = 0; i < 32; i += 2) {
        float4 r0 = Cc[(size_t)(i + 0) * (P / 4)];
        float4 r1 = Cc[(size_t)(i + 1) * (P / 4)];
        const float u0 = us[i], u1 = us[i + 1];
        p0 += ex2f(fmaf(r0.x, -K2E, u0) - ref0);
        p1 += ex2f(fmaf(r0.y, -K2E, u0) - ref1);
        p2 += ex2f(fmaf(r0.z, -K2E, u0) - ref2);
        p3 += ex2f(fmaf(r0.w, -K2E, u0) - ref3);
        q0 += ex2f(fmaf(r1.x, -K2E, u1) - ref0);
        q1 += ex2f(fmaf(r1.y, -K2E, u1) - ref1);
        q2 += ex2f(fmaf(r1.z, -K2E, u1) - ref2);
        q3 += ex2f(fmaf(r1.w, -K2E, u1) - ref3);
    }
    {
        float4 part = {p0 + q0, p1 + q1, p2 + q2, p3 + q3};
        *(float4*)&g_psF[((size_t)(n * 64 + ch)) * P + j0] = part;
    }

    __threadfence();
    if (tid == 0) pretick = atomicAdd(&g_tickM[n * 2 + jb], 1u);
    __syncthreads();
    if (pretick == 64u * (unsigned)(k + 1) - 1u) {       // winner for (n, jb)
        __threadfence();
        float ss0 = 0.0f, ss1 = 0.0f, ss2 = 0.0f, ss3 = 0.0f;
#pragma unroll 8
        for (int c = 0; c < 64; c++) {
            const float* pp = &g_psF[((size_t)(n * 64 + c)) * P + j0];
            ss0 += __ldcg(pp);
            ss1 += __ldcg(pp + 1);
            ss2 += __ldcg(pp + 2);
            ss3 += __ldcg(pp + 3);
        }
        g_vs2[(n << 11) + j0]     = (LOG_NU2 - ref0) - lg2f(ss0);
        g_vs2[(n << 11) + j0 + 1] = (LOG_NU2 - ref1) - lg2f(ss1);
        g_vs2[(n << 11) + j0 + 2] = (LOG_NU2 - ref2) - lg2f(ss2);
        g_vs2[(n << 11) + j0 + 3] = (LOG_NU2 - ref3) - lg2f(ss3);
    }
}

// ---------------- pi + cost partials ----------------------------------------------
__global__ __launch_bounds__(256) void pi_cost(const float* __restrict__ C,
                                               float* __restrict__ pi) {
    __shared__ float red[256];
    const int b = blockIdx.x;
    const int n = b >> 10;
    const float4* C4 = (const float4*)C;
    float4* P4 = (float4*)pi;
    const float4* V4 = (const float4*)(g_vs2 + (n << 11));
    const size_t base = (size_t)b * 1024;

    float acc = 0.0f;
#pragma unroll
    for (int p = 0; p < 4; p++) {
        size_t f4 = base + (size_t)p * 256 + threadIdx.x;
        float4 c = C4[f4];
        int ig = (int)(f4 >> 9);
        float u = g_us2[ig];
        float4 vv = V4[f4 & (P / 4 - 1)];
        float4 pv;
        pv.x = ex2f(fmaf(c.x, -K2E, u + vv.x));
        pv.y = ex2f(fmaf(c.y, -K2E, u + vv.y));
        pv.z = ex2f(fmaf(c.z, -K2E, u + vv.z));
        pv.w = ex2f(fmaf(c.w, -K2E, u + vv.w));
        P4[f4] = pv;
        acc += pv.x * c.x + pv.y * c.y + pv.z * c.z + pv.w * c.w;
    }
    red[threadIdx.x] = acc;
    __syncthreads();
#pragma unroll
    for (int o = 128; o; o >>= 1) {
        if (threadIdx.x < o) red[threadIdx.x] += red[threadIdx.x + o];
        __syncthreads();
    }
    if (threadIdx.x == 0) g_cp[b] = red[0];
}

__global__ __launch_bounds__(256) void cost_combine(float* __restrict__ cost) {
    __shared__ float red[256];
    const int n = blockIdx.x;
    float a = 0.0f;
#pragma unroll
    for (int q = 0; q < 4; q++)
        a += g_cp[n * 1024 + q * 256 + threadIdx.x];
    red[threadIdx.x] = a;
    __syncthreads();
#pragma unroll
    for (int o = 128; o; o >>= 1) {
        if (threadIdx.x < o) red[threadIdx.x] += red[threadIdx.x + o];
        __syncthreads();
    }
    if (threadIdx.x == 0) cost[n] = red[0];
}

// ---------------- launch --------------------------------------------------------------
extern "C" void kernel_launch(void* const* d_in, const int* in_sizes, int n_in,
                              void* d_out, int out_size) {
    const float* x = (const float*)d_in[0];
    const float* y = (const float*)d_in[1];
    float* out  = (float*)d_out;
    float* cost = out;
    float* pi   = out + NB;
    float* C    = out + NB + (size_t)NB * P * P;

    init_kernel<<<32, 256>>>();
    norms_kernel<<<NB * P / 256, 256>>>(x, y);
    c_kernel<<<dim3(P / 64, P / 64, NB), dim3(16, 16)>>>(x, y, C);

    for (int it = 0; it < ITERS; it++) {
        if (it < 2) {
            row_safe<<<NB * P / 8, 256>>>(C);
            col_safe<<<NB * RCH_S * JB_S, 256>>>(C);
        } else {
            iter_fast<<<NB * 128, 256>>>(C, it - 2);
        }
    }

    pi_cost<<<NB * 1024, 256>>>(C, pi);
    cost_combine<<<NB, 256>>>(cost);
}

// round 16
// speedup vs baseline: 1.4233x; 1.4233x over previous
#include <cuda_runtime.h>
#include <cstdint>
#include <cstddef>

#define NB 4
#define P  2048
#define D  64
#define ITERS   50
// safe col pass geometry (it < 2)
#define RCH_S   32
#define JB_S    4
// 10 * log2(e)
#define K2E 14.4269504089f
// log2(1/2048 + 1e-8)
#define LOG_MU2 (-10.99997045f)
#define LOG_NU2 (-10.99997045f)
#define NEG_BIG (-3.0e38f)

__device__ __forceinline__ float ex2f(float x) {
    float r; asm("ex2.approx.f32 %0, %1;" : "=f"(r) : "f"(x)); return r;
}
__device__ __forceinline__ float lg2f(float x) {
    float r; asm("lg2.approx.f32 %0, %1;" : "=f"(r) : "f"(x)); return r;
}

// ---------------- static device scratch -----------------------------------
__device__ float g_us2[NB * P];
__device__ float g_vs2[NB * P];
__device__ float g_xx[NB * P];
__device__ float g_yy[NB * P];
__device__ float g_pm2[NB * RCH_S * P];    // safe col partial max
__device__ float g_ps2[NB * RCH_S * P];    // col partial sums (both paths)
__device__ float g_cp[NB * 1024];
__device__ unsigned g_tick_s[NB * JB_S];   // safe path tickets (reset)
__device__ unsigned g_rowcnt[NB * 32];     // fast: monotone row-publish counters
__device__ unsigned g_tickM[NB * 4];       // fast: monotone v-combine tickets

// ---------------- init -------------------------------------------------------
__global__ void init_kernel() {
    int t = blockIdx.x * 256 + threadIdx.x;
    if (t < NB * P) g_vs2[t] = 0.0f;
    if (t < NB * JB_S) g_tick_s[t] = 0u;
    if (t < NB * 32) g_rowcnt[t] = 0u;
    if (t < NB * 4) g_tickM[t] = 0u;
}

// ---------------- squared norms ----------------------------------------------
__global__ __launch_bounds__(256) void norms_kernel(const float* __restrict__ x,
                                                    const float* __restrict__ y) {
    const int r = blockIdx.x * 256 + threadIdx.x;
    const float4* xr = (const float4*)(x + (size_t)r * D);
    const float4* yr = (const float4*)(y + (size_t)r * D);
    float ax = 0.0f, ay = 0.0f;
#pragma unroll
    for (int t = 0; t < D / 4; t++) {
        float4 a = xr[t], b = yr[t];
        ax = fmaf(a.x, a.x, ax); ax = fmaf(a.y, a.y, ax);
        ax = fmaf(a.z, a.z, ax); ax = fmaf(a.w, a.w, ax);
        ay = fmaf(b.x, b.x, ay); ay = fmaf(b.y, b.y, ay);
        ay = fmaf(b.z, b.z, ay); ay = fmaf(b.w, b.w, ay);
    }
    g_xx[r] = ax;
    g_yy[r] = ay;
}

// ---------------- C = xx_i + yy_j - 2*x.y ---------------------------------------
__global__ __launch_bounds__(256) void c_kernel(const float* __restrict__ x,
                                                const float* __restrict__ y,
                                                float* __restrict__ C) {
    __shared__ float Xs[64][68];
    __shared__ float Ys[64][68];
    const int tx = threadIdx.x, ty = threadIdx.y;
    const int tid = ty * 16 + tx;
    const int n  = blockIdx.z;
    const int i0 = blockIdx.y * 64;
    const int j0 = blockIdx.x * 64;

    {
        const int r  = tid >> 2;
        const int c4 = tid & 3;
        const float* xg = x + ((size_t)n * P + i0 + r) * D;
        const float* yg = y + ((size_t)n * P + j0 + r) * D;
#pragma unroll
        for (int q = 0; q < 4; q++) {
            int col = c4 * 16 + q * 4;
            *(float4*)&Xs[r][col] = *(const float4*)(xg + col);
            *(float4*)&Ys[r][col] = *(const float4*)(yg + col);
        }
    }
    __syncthreads();

    float acc[4][4];
#pragma unroll
    for (int a = 0; a < 4; a++)
#pragma unroll
        for (int b = 0; b < 4; b++) acc[a][b] = 0.0f;

#pragma unroll
    for (int k = 0; k < D; k += 4) {
        float4 xa[4], yb[4];
#pragma unroll
        for (int a = 0; a < 4; a++) xa[a] = *(float4*)&Xs[ty * 4 + a][k];
#pragma unroll
        for (int b = 0; b < 4; b++) yb[b] = *(float4*)&Ys[tx * 4 + b][k];
#pragma unroll
        for (int a = 0; a < 4; a++)
#pragma unroll
            for (int b = 0; b < 4; b++) {
                acc[a][b] = fmaf(xa[a].x, yb[b].x, acc[a][b]);
                acc[a][b] = fmaf(xa[a].y, yb[b].y, acc[a][b]);
                acc[a][b] = fmaf(xa[a].z, yb[b].z, acc[a][b]);
                acc[a][b] = fmaf(xa[a].w, yb[b].w, acc[a][b]);
            }
    }

    float yyv[4];
#pragma unroll
    for (int b = 0; b < 4; b++) yyv[b] = g_yy[(n << 11) + j0 + tx * 4 + b];

    float* Cb = C + (size_t)n * P * P;
#pragma unroll
    for (int a = 0; a < 4; a++) {
        float xxv = g_xx[(n << 11) + i0 + ty * 4 + a];
        float4 o;
        o.x = fmaf(-2.0f, acc[a][0], xxv + yyv[0]);
        o.y = fmaf(-2.0f, acc[a][1], xxv + yyv[1]);
        o.z = fmaf(-2.0f, acc[a][2], xxv + yyv[2]);
        o.w = fmaf(-2.0f, acc[a][3], xxv + yyv[3]);
        *(float4*)&Cb[(size_t)(i0 + ty * 4 + a) * P + j0 + tx * 4] = o;
    }
}

// ---------------- safe LSE helper -------------------------------------------------
__device__ __forceinline__ void lse_group(float4 c, float vx, float vy, float vz, float vw,
                                          float& m, float& s) {
    float b0 = fmaf(c.x, -K2E, vx);
    float b1 = fmaf(c.y, -K2E, vy);
    float b2 = fmaf(c.z, -K2E, vz);
    float b3 = fmaf(c.w, -K2E, vw);
    float cm = fmaxf(fmaxf(b0, b1), fmaxf(b2, b3));
    float mn = fmaxf(m, cm);
    s = fmaf(s, ex2f(m - mn),
             ex2f(b0 - mn) + ex2f(b1 - mn) + ex2f(b2 - mn) + ex2f(b3 - mn));
    m = mn;
}

// ================ SAFE path (it < 2) — proven R5 kernels ===========================
__global__ __launch_bounds__(256) void row_safe(const float* __restrict__ C) {
    __shared__ float vs[P];
    const int lane = threadIdx.x & 31;
    const int warp = threadIdx.x >> 5;
    const int row  = blockIdx.x * 8 + warp;
    const int n    = row >> 11;
    {
        const float4* src = (const float4*)(g_vs2 + (n << 11));
        float4* dst = (float4*)vs;
#pragma unroll
        for (int t = threadIdx.x; t < P / 4; t += 256) dst[t] = src[t];
    }
    __syncthreads();
    const float4* Crow = (const float4*)(C + (size_t)row * P);
    const float4* V4   = (const float4*)vs;
    float m0 = NEG_BIG, s0 = 0.0f, m1 = NEG_BIG, s1 = 0.0f;
#pragma unroll 4
    for (int k = 0; k < 8; k++) {
        const int t0 = lane + k * 64;
        const int t1 = t0 + 32;
        float4 c0 = Crow[t0];
        float4 c1 = Crow[t1];
        float4 v0 = V4[t0];
        float4 v1 = V4[t1];
        lse_group(c0, v0.x, v0.y, v0.z, v0.w, m0, s0);
        lse_group(c1, v1.x, v1.y, v1.z, v1.w, m1, s1);
    }
    float m = fmaxf(m0, m1);
    float s = s0 * ex2f(m0 - m) + s1 * ex2f(m1 - m);
#pragma unroll
    for (int o = 16; o; o >>= 1) {
        float mo = __shfl_xor_sync(0xffffffffu, m, o);
        float so = __shfl_xor_sync(0xffffffffu, s, o);
        float mn = fmaxf(m, mo);
        s = s * ex2f(m - mn) + so * ex2f(mo - mn);
        m = mn;
    }
    if (lane == 0) g_us2[row] = LOG_MU2 - (m + lg2f(s));
}

__global__ __launch_bounds__(256) void col_safe(const float* __restrict__ C) {
    __shared__ float us[P / RCH_S];
    __shared__ unsigned lastv;
    const int b     = blockIdx.x;
    const int jb    = b & (JB_S - 1);
    const int chunk = (b >> 2) & (RCH_S - 1);
    const int n     = b >> 7;
    const int j0    = (jb << 9) + (threadIdx.x << 1);
    const int i0    = chunk << 6;

    if (threadIdx.x < P / RCH_S)
        us[threadIdx.x] = g_us2[(n << 11) + i0 + threadIdx.x];
    __syncthreads();

    const float2* Cc = (const float2*)(C + (size_t)n * P * P + (size_t)i0 * P) + (j0 >> 1);
    const size_t po = ((size_t)n * RCH_S + chunk) * P + j0;

    float m0 = NEG_BIG, s0 = 0.0f, m1 = NEG_BIG, s1 = 0.0f;
#pragma unroll 4
    for (int i = 0; i < P / RCH_S; i += 4) {
        float2 r0 = Cc[(size_t)(i + 0) * (P / 2)];
        float2 r1 = Cc[(size_t)(i + 1) * (P / 2)];
        float2 r2 = Cc[(size_t)(i + 2) * (P / 2)];
        float2 r3 = Cc[(size_t)(i + 3) * (P / 2)];
        float4 c0 = {r0.x, r1.x, r2.x, r3.x};
        float4 c1 = {r0.y, r1.y, r2.y, r3.y};
        lse_group(c0, us[i], us[i + 1], us[i + 2], us[i + 3], m0, s0);
        lse_group(c1, us[i], us[i + 1], us[i + 2], us[i + 3], m1, s1);
    }
    g_pm2[po] = m0;     g_ps2[po] = s0;
    g_pm2[po + 1] = m1; g_ps2[po + 1] = s1;

    __threadfence();
    if (threadIdx.x == 0) lastv = atomicAdd(&g_tick_s[n * JB_S + jb], 1u);
    __syncthreads();
    if (lastv == RCH_S - 1) {
        __threadfence();
#pragma unroll
        for (int cc = 0; cc < 2; cc++) {
            const int j = j0 + cc;
            float mm = NEG_BIG;
#pragma unroll
            for (int c = 0; c < RCH_S; c++)
                mm = fmaxf(mm, __ldcg(&g_pm2[((size_t)n * RCH_S + c) * P + j]));
            float ss = 0.0f;
#pragma unroll
            for (int c = 0; c < RCH_S; c++) {
                size_t idx = ((size_t)n * RCH_S + c) * P + j;
                ss += __ldcg(&g_ps2[idx]) * ex2f(__ldcg(&g_pm2[idx]) - mm);
            }
            g_vs2[(n << 11) + j] = LOG_NU2 - (mm + lg2f(ss));
        }
        if (threadIdx.x == 0) g_tick_s[n * JB_S + jb] = 0u;
    }
}

// ================ FAST iteration (it >= 2): one launch, flag-pipelined =============
// 512 blocks x 256 threads, all co-resident.  Block (n, lb):
//   rows lb*16 .. lb*16+15 (row phase, ref-trick)
//   col task: chunk ch = lb>>2 (64 rows), jb = lb&3 (512 cols)
// Monotone counters: g_rowcnt (+16/block/iter), g_tickM (+1/block/iter).
__global__ __launch_bounds__(256, 4) void iter_fast(const float* __restrict__ C, int k) {
    __shared__ float vs[P];
    __shared__ float us[64];
    __shared__ unsigned pretick;
    const int tid  = threadIdx.x;
    const int lane = tid & 31;
    const int warp = tid >> 5;
    const int n    = blockIdx.x >> 7;
    const int lb   = blockIdx.x & 127;
    const int ch   = lb >> 2;
    const int jb   = lb & 3;

    // ---- load v (previous iteration, complete at kernel start) ------------------
    {
        const float4* src = (const float4*)(g_vs2 + (n << 11));
        float4* dst = (float4*)vs;
#pragma unroll
        for (int t = tid; t < P / 4; t += 256) dst[t] = src[t];
    }
    __syncthreads();

    // ---- row phase: 2 rows per warp, streaming (no mid-loop barriers) ------------
    const float4* V4 = (const float4*)vs;
    {
        const int rA = lb * 16 + warp * 2;
        const int gA = (n << 11) + rA;
        const int gB = gA + 1;
        const float4* CrA = (const float4*)(C + (size_t)gA * P);
        const float4* CrB = (const float4*)(C + (size_t)gB * P);
        const float upA = g_us2[gA];
        const float upB = g_us2[gB];
        const float refA = LOG_MU2 - upA;
        const float refB = LOG_MU2 - upB;
        float a0 = 0, a1 = 0, a2 = 0, a3 = 0;
        float b0 = 0, b1 = 0, b2 = 0, b3 = 0;
#pragma unroll 4
        for (int t = lane; t < P / 4; t += 32) {
            float4 cA = CrA[t];
            float4 cB = CrB[t];
            float4 vv = V4[t];
            a0 += ex2f(fmaf(cA.x, -K2E, vv.x) - refA);
            a1 += ex2f(fmaf(cA.y, -K2E, vv.y) - refA);
            a2 += ex2f(fmaf(cA.z, -K2E, vv.z) - refA);
            a3 += ex2f(fmaf(cA.w, -K2E, vv.w) - refA);
            b0 += ex2f(fmaf(cB.x, -K2E, vv.x) - refB);
            b1 += ex2f(fmaf(cB.y, -K2E, vv.y) - refB);
            b2 += ex2f(fmaf(cB.z, -K2E, vv.z) - refB);
            b3 += ex2f(fmaf(cB.w, -K2E, vv.w) - refB);
        }
        float sA = (a0 + a1) + (a2 + a3);
        float sB = (b0 + b1) + (b2 + b3);
#pragma unroll
        for (int o = 16; o; o >>= 1) {
            sA += __shfl_xor_sync(0xffffffffu, sA, o);
            sB += __shfl_xor_sync(0xffffffffu, sB, o);
        }
        if (lane == 0) {
            g_us2[gA] = upA - lg2f(sA);
            g_us2[gB] = upB - lg2f(sB);
        }
    }
    // publish: all 16 rows of this block done
    __syncthreads();
    __threadfence();
    if (tid == 0) atomicAdd(&g_rowcnt[n * 32 + (lb >> 2)], 16u);

    // ---- col phase: wait for own chunk's 64 rows ---------------------------------
    if (tid == 0) {
        const unsigned target = 64u * (unsigned)(k + 1);
        while (atomicAdd(&g_rowcnt[n * 32 + ch], 0u) < target) __nanosleep(32);
    }
    __syncthreads();
    __threadfence();
    if (tid < 64) us[tid] = __ldcg(&g_us2[(n << 11) + (ch << 6) + tid]);
    __syncthreads();

    const int j0 = (jb << 9) + (tid << 1);         // 2 cols per thread
    const float ref0 = LOG_NU2 - vs[j0];
    const float ref1 = LOG_NU2 - vs[j0 + 1];
    const float2* Cc = (const float2*)(C + (size_t)n * P * P + ((size_t)ch << 6) * P) + (j0 >> 1);

    float p0a = 0, p0b = 0, p1a = 0, p1b = 0;
#pragma unroll 4
    for (int i = 0; i < 64; i += 4) {
        float2 r0 = Cc[(size_t)(i + 0) * (P / 2)];
        float2 r1 = Cc[(size_t)(i + 1) * (P / 2)];
        float2 r2 = Cc[(size_t)(i + 2) * (P / 2)];
        float2 r3 = Cc[(size_t)(i + 3) * (P / 2)];
        p0a += ex2f(fmaf(r0.x, -K2E, us[i + 0]) - ref0);
        p1a += ex2f(fmaf(r0.y, -K2E, us[i + 0]) - ref1);
        p0b += ex2f(fmaf(r1.x, -K2E, us[i + 1]) - ref0);
        p1b += ex2f(fmaf(r1.y, -K2E, us[i + 1]) - ref1);
        p0a += ex2f(fmaf(r2.x, -K2E, us[i + 2]) - ref0);
        p1a += ex2f(fmaf(r2.y, -K2E, us[i + 2]) - ref1);
        p0b += ex2f(fmaf(r3.x, -K2E, us[i + 3]) - ref0);
        p1b += ex2f(fmaf(r3.y, -K2E, us[i + 3]) - ref1);
    }
    const size_t po = ((size_t)n * 32 + ch) * P + j0;
    g_ps2[po]     = p0a + p0b;
    g_ps2[po + 1] = p1a + p1b;

    __threadfence();
    if (tid == 0) pretick = atomicAdd(&g_tickM[n * 4 + jb], 1u);
    __syncthreads();
    if (pretick == 32u * (unsigned)(k + 1) - 1u) {      // winner for (n, jb)
        __threadfence();
        float ss0 = 0.0f, ss1 = 0.0f;
#pragma unroll 8
        for (int c = 0; c < 32; c++) {
            size_t idx = ((size_t)n * 32 + c) * P + j0;
            ss0 += __ldcg(&g_ps2[idx]);
            ss1 += __ldcg(&g_ps2[idx + 1]);
        }
        g_vs2[(n << 11) + j0]     = (LOG_NU2 - ref0) - lg2f(ss0);
        g_vs2[(n << 11) + j0 + 1] = (LOG_NU2 - ref1) - lg2f(ss1);
    }
}

// ---------------- pi + cost partials ----------------------------------------------
__global__ __launch_bounds__(256) void pi_cost(const float* __restrict__ C,
                                               float* __restrict__ pi) {
    __shared__ float red[256];
    const int b = blockIdx.x;
    const int n = b >> 10;
    const float4* C4 = (const float4*)C;
    float4* P4 = (float4*)pi;
    const float4* V4 = (const float4*)(g_vs2 + (n << 11));
    const size_t base = (size_t)b * 1024;

    float acc = 0.0f;
#pragma unroll
    for (int p = 0; p < 4; p++) {
        size_t f4 = base + (size_t)p * 256 + threadIdx.x;
        float4 c = C4[f4];
        int ig = (int)(f4 >> 9);
        float u = g_us2[ig];
        float4 vv = V4[f4 & (P / 4 - 1)];
        float4 pv;
        pv.x = ex2f(fmaf(c.x, -K2E, u + vv.x));
        pv.y = ex2f(fmaf(c.y, -K2E, u + vv.y));
        pv.z = ex2f(fmaf(c.z, -K2E, u + vv.z));
        pv.w = ex2f(fmaf(c.w, -K2E, u + vv.w));
        P4[f4] = pv;
        acc += pv.x * c.x + pv.y * c.y + pv.z * c.z + pv.w * c.w;
    }
    red[threadIdx.x] = acc;
    __syncthreads();
#pragma unroll
    for (int o = 128; o; o >>= 1) {
        if (threadIdx.x < o) red[threadIdx.x] += red[threadIdx.x + o];
        __syncthreads();
    }
    if (threadIdx.x == 0) g_cp[b] = red[0];
}

__global__ __launch_bounds__(256) void cost_combine(float* __restrict__ cost) {
    __shared__ float red[256];
    const int n = blockIdx.x;
    float a = 0.0f;
#pragma unroll
    for (int q = 0; q < 4; q++)
        a += g_cp[n * 1024 + q * 256 + threadIdx.x];
    red[threadIdx.x] = a;
    __syncthreads();
#pragma unroll
    for (int o = 128; o; o >>= 1) {
        if (threadIdx.x < o) red[threadIdx.x] += red[threadIdx.x + o];
        __syncthreads();
    }
    if (threadIdx.x == 0) cost[n] = red[0];
}

// ---------------- launch --------------------------------------------------------------
extern "C" void kernel_launch(void* const* d_in, const int* in_sizes, int n_in,
                              void* d_out, int out_size) {
    const float* x = (const float*)d_in[0];
    const float* y = (const float*)d_in[1];
    float* out  = (float*)d_out;
    float* cost = out;
    float* pi   = out + NB;
    float* C    = out + NB + (size_t)NB * P * P;

    init_kernel<<<32, 256>>>();
    norms_kernel<<<NB * P / 256, 256>>>(x, y);
    c_kernel<<<dim3(P / 64, P / 64, NB), dim3(16, 16)>>>(x, y, C);

    for (int it = 0; it < ITERS; it++) {
        if (it < 2) {
            row_safe<<<NB * P / 8, 256>>>(C);
            col_safe<<<NB * RCH_S * JB_S, 256>>>(C);
        } else {
            iter_fast<<<NB * 128, 256>>>(C, it - 2);
        }
    }

    pi_cost<<<NB * 1024, 256>>>(C, pi);
    cost_combine<<<NB, 256>>>(cost);
}

// round 17
// speedup vs baseline: 1.4317x; 1.0060x over previous
#include <cuda_runtime.h>
#include <cstdint>
#include <cstddef>

#define NB 4
#define P  2048
#define D  64
#define ITERS   50
#define SAFE_ITERS 1
// safe col pass geometry
#define RCH_S   32
#define JB_S    4
// 10 * log2(e)
#define K2E 14.4269504089f
// log2(1/2048 + 1e-8)
#define LOG_MU2 (-10.99997045f)
#define LOG_NU2 (-10.99997045f)
#define NEG_BIG (-3.0e38f)

__device__ __forceinline__ float ex2f(float x) {
    float r; asm("ex2.approx.f32 %0, %1;" : "=f"(r) : "f"(x)); return r;
}
__device__ __forceinline__ float lg2f(float x) {
    float r; asm("lg2.approx.f32 %0, %1;" : "=f"(r) : "f"(x)); return r;
}

// ---------------- static device scratch -----------------------------------
__device__ float g_us2[NB * P];
__device__ float g_vs2[NB * P];
__device__ float g_xx[NB * P];
__device__ float g_yy[NB * P];
__device__ float g_pm2[NB * RCH_S * P];    // safe col partial max
__device__ float g_ps2[NB * RCH_S * P];    // col partial sums (both paths)
__device__ float g_cp[NB * 1024];
__device__ unsigned g_tick_s[NB * JB_S];   // safe path tickets (reset)
__device__ unsigned g_rowcnt[NB * 32];     // fast: monotone row-publish counters
__device__ unsigned g_tickM[NB * 4];       // fast: monotone v-combine tickets

// ---------------- init -------------------------------------------------------
__global__ void init_kernel() {
    int t = blockIdx.x * 256 + threadIdx.x;
    if (t < NB * P) g_vs2[t] = 0.0f;
    if (t < NB * JB_S) g_tick_s[t] = 0u;
    if (t < NB * 32) g_rowcnt[t] = 0u;
    if (t < NB * 4) g_tickM[t] = 0u;
}

// ---------------- squared norms ----------------------------------------------
__global__ __launch_bounds__(256) void norms_kernel(const float* __restrict__ x,
                                                    const float* __restrict__ y) {
    const int r = blockIdx.x * 256 + threadIdx.x;
    const float4* xr = (const float4*)(x + (size_t)r * D);
    const float4* yr = (const float4*)(y + (size_t)r * D);
    float ax = 0.0f, ay = 0.0f;
#pragma unroll
    for (int t = 0; t < D / 4; t++) {
        float4 a = xr[t], b = yr[t];
        ax = fmaf(a.x, a.x, ax); ax = fmaf(a.y, a.y, ax);
        ax = fmaf(a.z, a.z, ax); ax = fmaf(a.w, a.w, ax);
        ay = fmaf(b.x, b.x, ay); ay = fmaf(b.y, b.y, ay);
        ay = fmaf(b.z, b.z, ay); ay = fmaf(b.w, b.w, ay);
    }
    g_xx[r] = ax;
    g_yy[r] = ay;
}

// ---------------- C = xx_i + yy_j - 2*x.y ---------------------------------------
__global__ __launch_bounds__(256) void c_kernel(const float* __restrict__ x,
                                                const float* __restrict__ y,
                                                float* __restrict__ C) {
    __shared__ float Xs[64][68];
    __shared__ float Ys[64][68];
    const int tx = threadIdx.x, ty = threadIdx.y;
    const int tid = ty * 16 + tx;
    const int n  = blockIdx.z;
    const int i0 = blockIdx.y * 64;
    const int j0 = blockIdx.x * 64;

    {
        const int r  = tid >> 2;
        const int c4 = tid & 3;
        const float* xg = x + ((size_t)n * P + i0 + r) * D;
        const float* yg = y + ((size_t)n * P + j0 + r) * D;
#pragma unroll
        for (int q = 0; q < 4; q++) {
            int col = c4 * 16 + q * 4;
            *(float4*)&Xs[r][col] = *(const float4*)(xg + col);
            *(float4*)&Ys[r][col] = *(const float4*)(yg + col);
        }
    }
    __syncthreads();

    float acc[4][4];
#pragma unroll
    for (int a = 0; a < 4; a++)
#pragma unroll
        for (int b = 0; b < 4; b++) acc[a][b] = 0.0f;

#pragma unroll
    for (int k = 0; k < D; k += 4) {
        float4 xa[4], yb[4];
#pragma unroll
        for (int a = 0; a < 4; a++) xa[a] = *(float4*)&Xs[ty * 4 + a][k];
#pragma unroll
        for (int b = 0; b < 4; b++) yb[b] = *(float4*)&Ys[tx * 4 + b][k];
#pragma unroll
        for (int a = 0; a < 4; a++)
#pragma unroll
            for (int b = 0; b < 4; b++) {
                acc[a][b] = fmaf(xa[a].x, yb[b].x, acc[a][b]);
                acc[a][b] = fmaf(xa[a].y, yb[b].y, acc[a][b]);
                acc[a][b] = fmaf(xa[a].z, yb[b].z, acc[a][b]);
                acc[a][b] = fmaf(xa[a].w, yb[b].w, acc[a][b]);
            }
    }

    float yyv[4];
#pragma unroll
    for (int b = 0; b < 4; b++) yyv[b] = g_yy[(n << 11) + j0 + tx * 4 + b];

    float* Cb = C + (size_t)n * P * P;
#pragma unroll
    for (int a = 0; a < 4; a++) {
        float xxv = g_xx[(n << 11) + i0 + ty * 4 + a];
        float4 o;
        o.x = fmaf(-2.0f, acc[a][0], xxv + yyv[0]);
        o.y = fmaf(-2.0f, acc[a][1], xxv + yyv[1]);
        o.z = fmaf(-2.0f, acc[a][2], xxv + yyv[2]);
        o.w = fmaf(-2.0f, acc[a][3], xxv + yyv[3]);
        *(float4*)&Cb[(size_t)(i0 + ty * 4 + a) * P + j0 + tx * 4] = o;
    }
}

// ---------------- safe LSE helper -------------------------------------------------
__device__ __forceinline__ void lse_group(float4 c, float vx, float vy, float vz, float vw,
                                          float& m, float& s) {
    float b0 = fmaf(c.x, -K2E, vx);
    float b1 = fmaf(c.y, -K2E, vy);
    float b2 = fmaf(c.z, -K2E, vz);
    float b3 = fmaf(c.w, -K2E, vw);
    float cm = fmaxf(fmaxf(b0, b1), fmaxf(b2, b3));
    float mn = fmaxf(m, cm);
    s = fmaf(s, ex2f(m - mn),
             ex2f(b0 - mn) + ex2f(b1 - mn) + ex2f(b2 - mn) + ex2f(b3 - mn));
    m = mn;
}

// ================ SAFE path (it = 0) — proven R5 kernels ===========================
__global__ __launch_bounds__(256) void row_safe(const float* __restrict__ C) {
    __shared__ float vs[P];
    const int lane = threadIdx.x & 31;
    const int warp = threadIdx.x >> 5;
    const int row  = blockIdx.x * 8 + warp;
    const int n    = row >> 11;
    {
        const float4* src = (const float4*)(g_vs2 + (n << 11));
        float4* dst = (float4*)vs;
#pragma unroll
        for (int t = threadIdx.x; t < P / 4; t += 256) dst[t] = src[t];
    }
    __syncthreads();
    const float4* Crow = (const float4*)(C + (size_t)row * P);
    const float4* V4   = (const float4*)vs;
    float m0 = NEG_BIG, s0 = 0.0f, m1 = NEG_BIG, s1 = 0.0f;
#pragma unroll 4
    for (int k = 0; k < 8; k++) {
        const int t0 = lane + k * 64;
        const int t1 = t0 + 32;
        float4 c0 = Crow[t0];
        float4 c1 = Crow[t1];
        float4 v0 = V4[t0];
        float4 v1 = V4[t1];
        lse_group(c0, v0.x, v0.y, v0.z, v0.w, m0, s0);
        lse_group(c1, v1.x, v1.y, v1.z, v1.w, m1, s1);
    }
    float m = fmaxf(m0, m1);
    float s = s0 * ex2f(m0 - m) + s1 * ex2f(m1 - m);
#pragma unroll
    for (int o = 16; o; o >>= 1) {
        float mo = __shfl_xor_sync(0xffffffffu, m, o);
        float so = __shfl_xor_sync(0xffffffffu, s, o);
        float mn = fmaxf(m, mo);
        s = s * ex2f(m - mn) + so * ex2f(mo - mn);
        m = mn;
    }
    if (lane == 0) g_us2[row] = LOG_MU2 - (m + lg2f(s));
}

__global__ __launch_bounds__(256) void col_safe(const float* __restrict__ C) {
    __shared__ float us[P / RCH_S];
    __shared__ unsigned lastv;
    const int b     = blockIdx.x;
    const int jb    = b & (JB_S - 1);
    const int chunk = (b >> 2) & (RCH_S - 1);
    const int n     = b >> 7;
    const int j0    = (jb << 9) + (threadIdx.x << 1);
    const int i0    = chunk << 6;

    if (threadIdx.x < P / RCH_S)
        us[threadIdx.x] = g_us2[(n << 11) + i0 + threadIdx.x];
    __syncthreads();

    const float2* Cc = (const float2*)(C + (size_t)n * P * P + (size_t)i0 * P) + (j0 >> 1);
    const size_t po = ((size_t)n * RCH_S + chunk) * P + j0;

    float m0 = NEG_BIG, s0 = 0.0f, m1 = NEG_BIG, s1 = 0.0f;
#pragma unroll 4
    for (int i = 0; i < P / RCH_S; i += 4) {
        float2 r0 = Cc[(size_t)(i + 0) * (P / 2)];
        float2 r1 = Cc[(size_t)(i + 1) * (P / 2)];
        float2 r2 = Cc[(size_t)(i + 2) * (P / 2)];
        float2 r3 = Cc[(size_t)(i + 3) * (P / 2)];
        float4 c0 = {r0.x, r1.x, r2.x, r3.x};
        float4 c1 = {r0.y, r1.y, r2.y, r3.y};
        lse_group(c0, us[i], us[i + 1], us[i + 2], us[i + 3], m0, s0);
        lse_group(c1, us[i], us[i + 1], us[i + 2], us[i + 3], m1, s1);
    }
    g_pm2[po] = m0;     g_ps2[po] = s0;
    g_pm2[po + 1] = m1; g_ps2[po + 1] = s1;

    __threadfence();
    if (threadIdx.x == 0) lastv = atomicAdd(&g_tick_s[n * JB_S + jb], 1u);
    __syncthreads();
    if (lastv == RCH_S - 1) {
        __threadfence();
#pragma unroll
        for (int cc = 0; cc < 2; cc++) {
            const int j = j0 + cc;
            float mm = NEG_BIG;
#pragma unroll
            for (int c = 0; c < RCH_S; c++)
                mm = fmaxf(mm, __ldcg(&g_pm2[((size_t)n * RCH_S + c) * P + j]));
            float ss = 0.0f;
#pragma unroll
            for (int c = 0; c < RCH_S; c++) {
                size_t idx = ((size_t)n * RCH_S + c) * P + j;
                ss += __ldcg(&g_ps2[idx]) * ex2f(__ldcg(&g_pm2[idx]) - mm);
            }
            g_vs2[(n << 11) + j] = LOG_NU2 - (mm + lg2f(ss));
        }
        if (threadIdx.x == 0) g_tick_s[n * JB_S + jb] = 0u;
    }
}

// ================ FAST iteration (it >= 1): one launch, flag-pipelined =============
// 512 blocks x 256 threads, all co-resident.  Block (n, lb):
//   rows lb*16 .. lb*16+15 (row phase, ref-trick)
//   col task: chunk ch = lb>>2 (64 rows), jb = lb&3 (512 cols)
// Monotone counters: g_rowcnt (+16/block/iter), g_tickM (+1/block/iter).
__global__ __launch_bounds__(256, 4) void iter_fast(const float* __restrict__ C, int k) {
    __shared__ float vs[P];
    __shared__ float us[64];
    __shared__ unsigned pretick;
    const int tid  = threadIdx.x;
    const int lane = tid & 31;
    const int warp = tid >> 5;
    const int n    = blockIdx.x >> 7;
    const int lb   = blockIdx.x & 127;
    const int ch   = lb >> 2;
    const int jb   = lb & 3;

    // ---- load v (previous iteration, complete at kernel start) ------------------
    {
        const float4* src = (const float4*)(g_vs2 + (n << 11));
        float4* dst = (float4*)vs;
#pragma unroll
        for (int t = tid; t < P / 4; t += 256) dst[t] = src[t];
    }
    __syncthreads();

    // ---- row phase: 2 rows per warp, streaming (no mid-loop barriers) ------------
    const float4* V4 = (const float4*)vs;
    {
        const int rA = lb * 16 + warp * 2;
        const int gA = (n << 11) + rA;
        const int gB = gA + 1;
        const float4* CrA = (const float4*)(C + (size_t)gA * P);
        const float4* CrB = (const float4*)(C + (size_t)gB * P);
        const float upA = g_us2[gA];
        const float upB = g_us2[gB];
        const float refA = LOG_MU2 - upA;
        const float refB = LOG_MU2 - upB;
        float a0 = 0, a1 = 0, a2 = 0, a3 = 0;
        float b0 = 0, b1 = 0, b2 = 0, b3 = 0;
#pragma unroll 4
        for (int t = lane; t < P / 4; t += 32) {
            float4 cA = CrA[t];
            float4 cB = CrB[t];
            float4 vv = V4[t];
            a0 += ex2f(fmaf(cA.x, -K2E, vv.x) - refA);
            a1 += ex2f(fmaf(cA.y, -K2E, vv.y) - refA);
            a2 += ex2f(fmaf(cA.z, -K2E, vv.z) - refA);
            a3 += ex2f(fmaf(cA.w, -K2E, vv.w) - refA);
            b0 += ex2f(fmaf(cB.x, -K2E, vv.x) - refB);
            b1 += ex2f(fmaf(cB.y, -K2E, vv.y) - refB);
            b2 += ex2f(fmaf(cB.z, -K2E, vv.z) - refB);
            b3 += ex2f(fmaf(cB.w, -K2E, vv.w) - refB);
        }
        float sA = (a0 + a1) + (a2 + a3);
        float sB = (b0 + b1) + (b2 + b3);
#pragma unroll
        for (int o = 16; o; o >>= 1) {
            sA += __shfl_xor_sync(0xffffffffu, sA, o);
            sB += __shfl_xor_sync(0xffffffffu, sB, o);
        }
        if (lane == 0) {
            g_us2[gA] = upA - lg2f(sA);
            g_us2[gB] = upB - lg2f(sB);
        }
    }
    // publish: all 16 rows of this block done
    __syncthreads();
    __threadfence();
    if (tid == 0) atomicAdd(&g_rowcnt[n * 32 + (lb >> 2)], 16u);

    // ---- col phase: wait for own chunk's 64 rows ---------------------------------
    if (tid == 0) {
        const unsigned target = 64u * (unsigned)(k + 1);
        while (atomicAdd(&g_rowcnt[n * 32 + ch], 0u) < target) __nanosleep(32);
    }
    __syncthreads();
    __threadfence();
    if (tid < 64) us[tid] = __ldcg(&g_us2[(n << 11) + (ch << 6) + tid]);
    __syncthreads();

    const int j0 = (jb << 9) + (tid << 1);         // 2 cols per thread
    const float ref0 = LOG_NU2 - vs[j0];
    const float ref1 = LOG_NU2 - vs[j0 + 1];
    const float2* Cc = (const float2*)(C + (size_t)n * P * P + ((size_t)ch << 6) * P) + (j0 >> 1);

    float p0a = 0, p0b = 0, p1a = 0, p1b = 0;
#pragma unroll 4
    for (int i = 0; i < 64; i += 4) {
        float2 r0 = Cc[(size_t)(i + 0) * (P / 2)];
        float2 r1 = Cc[(size_t)(i + 1) * (P / 2)];
        float2 r2 = Cc[(size_t)(i + 2) * (P / 2)];
        float2 r3 = Cc[(size_t)(i + 3) * (P / 2)];
        p0a += ex2f(fmaf(r0.x, -K2E, us[i + 0]) - ref0);
        p1a += ex2f(fmaf(r0.y, -K2E, us[i + 0]) - ref1);
        p0b += ex2f(fmaf(r1.x, -K2E, us[i + 1]) - ref0);
        p1b += ex2f(fmaf(r1.y, -K2E, us[i + 1]) - ref1);
        p0a += ex2f(fmaf(r2.x, -K2E, us[i + 2]) - ref0);
        p1a += ex2f(fmaf(r2.y, -K2E, us[i + 2]) - ref1);
        p0b += ex2f(fmaf(r3.x, -K2E, us[i + 3]) - ref0);
        p1b += ex2f(fmaf(r3.y, -K2E, us[i + 3]) - ref1);
    }
    const size_t po = ((size_t)n * 32 + ch) * P + j0;
    g_ps2[po]     = p0a + p0b;
    g_ps2[po + 1] = p1a + p1b;

    __threadfence();
    if (tid == 0) pretick = atomicAdd(&g_tickM[n * 4 + jb], 1u);
    __syncthreads();
    if (pretick == 32u * (unsigned)(k + 1) - 1u) {      // winner for (n, jb)
        __threadfence();
        float ss0 = 0.0f, ss1 = 0.0f;
#pragma unroll 8
        for (int c = 0; c < 32; c++) {
            size_t idx = ((size_t)n * 32 + c) * P + j0;
            ss0 += __ldcg(&g_ps2[idx]);
            ss1 += __ldcg(&g_ps2[idx + 1]);
        }
        g_vs2[(n << 11) + j0]     = (LOG_NU2 - ref0) - lg2f(ss0);
        g_vs2[(n << 11) + j0 + 1] = (LOG_NU2 - ref1) - lg2f(ss1);
    }
}

// ---------------- pi + cost partials ----------------------------------------------
__global__ __launch_bounds__(256) void pi_cost(const float* __restrict__ C,
                                               float* __restrict__ pi) {
    __shared__ float red[256];
    const int b = blockIdx.x;
    const int n = b >> 10;
    const float4* C4 = (const float4*)C;
    float4* P4 = (float4*)pi;
    const float4* V4 = (const float4*)(g_vs2 + (n << 11));
    const size_t base = (size_t)b * 1024;

    float acc = 0.0f;
#pragma unroll
    for (int p = 0; p < 4; p++) {
        size_t f4 = base + (size_t)p * 256 + threadIdx.x;
        float4 c = C4[f4];
        int ig = (int)(f4 >> 9);
        float u = g_us2[ig];
        float4 vv = V4[f4 & (P / 4 - 1)];
        float4 pv;
        pv.x = ex2f(fmaf(c.x, -K2E, u + vv.x));
        pv.y = ex2f(fmaf(c.y, -K2E, u + vv.y));
        pv.z = ex2f(fmaf(c.z, -K2E, u + vv.z));
        pv.w = ex2f(fmaf(c.w, -K2E, u + vv.w));
        P4[f4] = pv;
        acc += pv.x * c.x + pv.y * c.y + pv.z * c.z + pv.w * c.w;
    }
    red[threadIdx.x] = acc;
    __syncthreads();
#pragma unroll
    for (int o = 128; o; o >>= 1) {
        if (threadIdx.x < o) red[threadIdx.x] += red[threadIdx.x + o];
        __syncthreads();
    }
    if (threadIdx.x == 0) g_cp[b] = red[0];
}

__global__ __launch_bounds__(256) void cost_combine(float* __restrict__ cost) {
    __shared__ float red[256];
    const int n = blockIdx.x;
    float a = 0.0f;
#pragma unroll
    for (int q = 0; q < 4; q++)
        a += g_cp[n * 1024 + q * 256 + threadIdx.x];
    red[threadIdx.x] = a;
    __syncthreads();
#pragma unroll
    for (int o = 128; o; o >>= 1) {
        if (threadIdx.x < o) red[threadIdx.x] += red[threadIdx.x + o];
        __syncthreads();
    }
    if (threadIdx.x == 0) cost[n] = red[0];
}

// ---------------- launch --------------------------------------------------------------
extern "C" void kernel_launch(void* const* d_in, const int* in_sizes, int n_in,
                              void* d_out, int out_size) {
    const float* x = (const float*)d_in[0];
    const float* y = (const float*)d_in[1];
    float* out  = (float*)d_out;
    float* cost = out;
    float* pi   = out + NB;
    float* C    = out + NB + (size_t)NB * P * P;

    init_kernel<<<32, 256>>>();
    norms_kernel<<<NB * P / 256, 256>>>(x, y);
    c_kernel<<<dim3(P / 64, P / 64, NB), dim3(16, 16)>>>(x, y, C);

    for (int it = 0; it < ITERS; it++) {
        if (it < SAFE_ITERS) {
            row_safe<<<NB * P / 8, 256>>>(C);
            col_safe<<<NB * RCH_S * JB_S, 256>>>(C);
        } else {
            iter_fast<<<NB * 128, 256>>>(C, it - SAFE_ITERS);
        }
    }

    pi_cost<<<NB * 1024, 256>>>(C, pi);
    cost_combine<<<NB, 256>>>(cost);
}